// round 1
// baseline (speedup 1.0000x reference)
#include <cuda_runtime.h>
#include <math.h>

// Problem dims (fixed by the dataset)
#define AR 8192   // rows of seq1
#define BR 8192   // rows of seq2
#define ED 1024   // E1 == E2
#define MD 1024   // M

// ---------------- device scratch (allocation-free rule: static globals) ----
__device__ float g_p1[(size_t)AR * MD];   // elu(seq1 @ W1.T + b1 + ctx1)
__device__ float g_p2[(size_t)BR * MD];
__device__ float g_s1[MD];                // column sums of p1
__device__ float g_s2[MD];                // column sums of p2
__device__ float g_bias1[MD];             // b1 + W_ctx1 @ c
__device__ float g_bias2[MD];             // b2 + W_ctx2 @ c
__device__ float g_logits[2 * AR];        // [0:AR) = logits_a, [AR:2AR) = logits_b
__device__ float g_wexp[2 * AR];          // softmax weights

__device__ __forceinline__ float elu1(float x) {
    return x > 0.0f ? x : expm1f(x);
}

// ---------------- 0) zero accumulators + output ---------------------------
__global__ void zero_kernel(float* out) {
    int i = blockIdx.x * blockDim.x + threadIdx.x;
    if (i < MD) { g_s1[i] = 0.0f; g_s2[i] = 0.0f; }
    if (i < 2 * ED) out[i] = 0.0f;
}

// ---------------- 1) ctx GEMVs: bias' = b + W_ctx @ c ----------------------
// 2048 rows total (2 matrices x 1024 rows), one warp per row.
__global__ void ctx_kernel(const float* __restrict__ ctx,
                           const float* __restrict__ Wc1,
                           const float* __restrict__ Wc2,
                           const float* __restrict__ b1,
                           const float* __restrict__ b2) {
    int g = blockIdx.x * (blockDim.x >> 5) + (threadIdx.x >> 5);
    int lane = threadIdx.x & 31;
    int mat = g >> 10;          // 0 or 1
    int row = g & 1023;
    const float* W = mat ? Wc2 : Wc1;
    const float* b = mat ? b2 : b1;
    float* out = mat ? g_bias2 : g_bias1;
    float acc = 0.0f;
    const float* wr = W + (size_t)row * ED;
    for (int k = lane; k < ED; k += 32) acc += wr[k] * ctx[k];
    #pragma unroll
    for (int o = 16; o > 0; o >>= 1) acc += __shfl_down_sync(0xffffffffu, acc, o);
    if (lane == 0) out[row] = b[row] + acc;
}

// ---------------- 2) GEMM + elu + column-sum epilogue ----------------------
// P[i,m] = elu( sum_e A[i,e]*W[m,e] + bias[m] ),  S[m] += column sums.
// 128x128 block tile, BK=16, 256 threads, 8x8 microtile (2x2 of 4x4 groups).
#define BK 16
__global__ __launch_bounds__(256, 2)
void gemm_elu_kernel(const float* __restrict__ A,
                     const float* __restrict__ W,
                     const float* __restrict__ bias,
                     float* __restrict__ P,
                     float* __restrict__ S) {
    __shared__ __align__(16) float As[BK][132];
    __shared__ __align__(16) float Ws[BK][132];

    const int t = threadIdx.x;
    const int tx = t & 15;        // 0..15 -> column groups
    const int ty = t >> 4;        // 0..15 -> row groups
    const int rowBlock = blockIdx.y * 128;
    const int colBlock = blockIdx.x * 128;

    float acc[8][8];
    #pragma unroll
    for (int i = 0; i < 8; i++)
        #pragma unroll
        for (int j = 0; j < 8; j++) acc[i][j] = 0.0f;

    for (int k0 = 0; k0 < ED; k0 += BK) {
        // cooperative load: 128 rows x 16 K for both A and W tiles (float4)
        #pragma unroll
        for (int l = 0; l < 2; l++) {
            int f4 = t + l * 256;        // 0..511
            int r  = f4 >> 2;            // 0..127
            int kq = (f4 & 3) << 2;      // 0,4,8,12
            float4 va = *(const float4*)&A[(size_t)(rowBlock + r) * ED + k0 + kq];
            As[kq + 0][r] = va.x; As[kq + 1][r] = va.y;
            As[kq + 2][r] = va.z; As[kq + 3][r] = va.w;
            float4 vw = *(const float4*)&W[(size_t)(colBlock + r) * ED + k0 + kq];
            Ws[kq + 0][r] = vw.x; Ws[kq + 1][r] = vw.y;
            Ws[kq + 2][r] = vw.z; Ws[kq + 3][r] = vw.w;
        }
        __syncthreads();

        #pragma unroll
        for (int k = 0; k < BK; k++) {
            float a[8], b[8];
            *(float4*)&a[0] = *(const float4*)&As[k][ty * 4];
            *(float4*)&a[4] = *(const float4*)&As[k][64 + ty * 4];
            *(float4*)&b[0] = *(const float4*)&Ws[k][tx * 4];
            *(float4*)&b[4] = *(const float4*)&Ws[k][64 + tx * 4];
            #pragma unroll
            for (int i = 0; i < 8; i++)
                #pragma unroll
                for (int j = 0; j < 8; j++)
                    acc[i][j] += a[i] * b[j];
        }
        __syncthreads();
    }

    // epilogue: + bias, elu, store (coalesced float4), column-sum atomics
    float bv[8];
    *(float4*)&bv[0] = *(const float4*)&bias[colBlock + tx * 4];
    *(float4*)&bv[4] = *(const float4*)&bias[colBlock + 64 + tx * 4];

    float csum[8];
    #pragma unroll
    for (int j = 0; j < 8; j++) csum[j] = 0.0f;

    #pragma unroll
    for (int i = 0; i < 8; i++) {
        int r = rowBlock + ((i < 4) ? (ty * 4 + i) : (64 + ty * 4 + (i - 4)));
        float4 o0, o1;
        o0.x = elu1(acc[i][0] + bv[0]); csum[0] += o0.x;
        o0.y = elu1(acc[i][1] + bv[1]); csum[1] += o0.y;
        o0.z = elu1(acc[i][2] + bv[2]); csum[2] += o0.z;
        o0.w = elu1(acc[i][3] + bv[3]); csum[3] += o0.w;
        o1.x = elu1(acc[i][4] + bv[4]); csum[4] += o1.x;
        o1.y = elu1(acc[i][5] + bv[5]); csum[5] += o1.y;
        o1.z = elu1(acc[i][6] + bv[6]); csum[6] += o1.z;
        o1.w = elu1(acc[i][7] + bv[7]); csum[7] += o1.w;
        *(float4*)&P[(size_t)r * MD + colBlock + tx * 4] = o0;
        *(float4*)&P[(size_t)r * MD + colBlock + 64 + tx * 4] = o1;
    }
    #pragma unroll
    for (int j = 0; j < 8; j++) {
        int c = colBlock + ((j < 4) ? (tx * 4 + j) : (64 + tx * 4 + (j - 4)));
        atomicAdd(&S[c], csum[j]);
    }
}

// ---------------- 3) logits GEMV: logits_a = p1 @ s2, logits_b = p2 @ s1 ---
// One warp per row; 8 warps/block; grid = 2048 blocks (1024 per matrix).
__global__ void logits_kernel() {
    __shared__ float s[MD];
    int mat = blockIdx.x >> 10;
    const float* P = mat ? g_p2 : g_p1;
    const float* S = mat ? g_s1 : g_s2;      // cross-coupled sums
    float* L = g_logits + mat * AR;

    for (int i = threadIdx.x; i < MD; i += blockDim.x) s[i] = S[i];
    __syncthreads();

    int wid = threadIdx.x >> 5, lane = threadIdx.x & 31;
    int row = (blockIdx.x & 1023) * 8 + wid;
    const float* p = P + (size_t)row * MD;
    float acc = 0.0f;
    #pragma unroll 4
    for (int k = lane; k < MD; k += 32) acc += p[k] * s[k];
    #pragma unroll
    for (int o = 16; o > 0; o >>= 1) acc += __shfl_down_sync(0xffffffffu, acc, o);
    if (lane == 0) L[row] = acc;
}

// ---------------- 4) softmax over 8192 logits (one block per matrix) -------
__global__ void softmax_kernel() {
    __shared__ float red[1024];
    int mat = blockIdx.x;
    const float* L = g_logits + mat * AR;
    float* W = g_wexp + mat * AR;
    int t = threadIdx.x;

    float m = -INFINITY;
    for (int i = t; i < AR; i += 1024) m = fmaxf(m, L[i]);
    red[t] = m; __syncthreads();
    for (int o = 512; o > 0; o >>= 1) {
        if (t < o) red[t] = fmaxf(red[t], red[t + o]);
        __syncthreads();
    }
    m = red[0];
    __syncthreads();

    float z = 0.0f;
    for (int i = t; i < AR; i += 1024) z += expf(L[i] - m);
    red[t] = z; __syncthreads();
    for (int o = 512; o > 0; o >>= 1) {
        if (t < o) red[t] += red[t + o];
        __syncthreads();
    }
    float inv = 1.0f / red[0];
    for (int i = t; i < AR; i += 1024) W[i] = expf(L[i] - m) * inv;
}

// ---------------- 5) att = seq.T @ w  (weighted column reduction) ----------
// grid (4 col-chunks, 16 row-chunks, 2 matrices), 256 threads = 1 col each.
__global__ void att_kernel(const float* __restrict__ seq1,
                           const float* __restrict__ seq2,
                           float* __restrict__ out) {
    int mat = blockIdx.z;
    const float* Sq = mat ? seq2 : seq1;
    const float* W  = g_wexp + mat * AR;
    int c  = blockIdx.x * 256 + threadIdx.x;
    int r0 = blockIdx.y * 512;

    float acc0 = 0.0f, acc1 = 0.0f;
    #pragma unroll 4
    for (int r = r0; r < r0 + 512; r += 2) {
        acc0 += Sq[(size_t)r * ED + c] * W[r];
        acc1 += Sq[(size_t)(r + 1) * ED + c] * W[r + 1];
    }
    atomicAdd(&out[mat * ED + c], acc0 + acc1);
}

// ---------------- launch ----------------------------------------------------
extern "C" void kernel_launch(void* const* d_in, const int* in_sizes, int n_in,
                              void* d_out, int out_size) {
    const float* seq1  = (const float*)d_in[0];   // [8192,1024]
    const float* seq2  = (const float*)d_in[1];   // [8192,1024]
    const float* ctx   = (const float*)d_in[2];   // [1024]
    const float* Wc1   = (const float*)d_in[3];   // [1024,1024]
    const float* Wc2   = (const float*)d_in[4];   // [1024,1024]
    const float* W1    = (const float*)d_in[5];   // [1024,1024]
    const float* b1    = (const float*)d_in[6];   // [1024]
    const float* W2    = (const float*)d_in[7];   // [1024,1024]
    const float* b2    = (const float*)d_in[8];   // [1024]
    float* out = (float*)d_out;                   // [2048] = att1 ++ att2

    float *p1, *p2, *s1, *s2, *bias1, *bias2;
    cudaGetSymbolAddress((void**)&p1, g_p1);
    cudaGetSymbolAddress((void**)&p2, g_p2);
    cudaGetSymbolAddress((void**)&s1, g_s1);
    cudaGetSymbolAddress((void**)&s2, g_s2);
    cudaGetSymbolAddress((void**)&bias1, g_bias1);
    cudaGetSymbolAddress((void**)&bias2, g_bias2);

    zero_kernel<<<16, 256>>>(out);
    ctx_kernel<<<256, 256>>>(ctx, Wc1, Wc2, b1, b2);

    dim3 ggrid(MD / 128, AR / 128);
    gemm_elu_kernel<<<ggrid, 256>>>(seq1, W1, bias1, p1, s1);
    gemm_elu_kernel<<<ggrid, 256>>>(seq2, W2, bias2, p2, s2);

    logits_kernel<<<2048, 256>>>();
    softmax_kernel<<<2, 1024>>>();

    att_kernel<<<dim3(ED / 256, AR / 512, 2), 256>>>(seq1, seq2, out);
}

// round 3
// speedup vs baseline: 4.2399x; 4.2399x over previous
#include <cuda_runtime.h>
#include <cuda_bf16.h>
#include <math.h>
#include <stdint.h>

#define AR 8192
#define ED 1024
#define MD 1024

// ---------------- device scratch ----------------
__device__ __nv_bfloat16 g_a1[(size_t)AR * ED];
__device__ __nv_bfloat16 g_a2[(size_t)AR * ED];
__device__ __nv_bfloat16 g_wb1[(size_t)MD * ED];
__device__ __nv_bfloat16 g_wb2[(size_t)MD * ED];
__device__ __nv_bfloat16 g_p1[(size_t)AR * MD];
__device__ __nv_bfloat16 g_p2[(size_t)AR * MD];
__device__ float g_s1[MD];
__device__ float g_s2[MD];
__device__ float g_bias1[MD];
__device__ float g_bias2[MD];
__device__ float g_logits[2 * AR];
__device__ float g_wexp[2 * AR];

__device__ __forceinline__ float elu1(float x) { return x > 0.0f ? x : expm1f(x); }

__device__ __forceinline__ uint32_t smem_u32(const void* p) {
    uint32_t a;
    asm("{ .reg .u64 t; cvta.to.shared.u64 t, %1; cvt.u32.u64 %0, t; }" : "=r"(a) : "l"(p));
    return a;
}
#define CP_ASYNC16(dst, src) \
    asm volatile("cp.async.cg.shared.global [%0], [%1], 16;" :: "r"(dst), "l"(src))
#define CP_COMMIT() asm volatile("cp.async.commit_group;" ::: "memory")
#define CP_WAIT1()  asm volatile("cp.async.wait_group 1;" ::: "memory")
#define LDMATRIX_X4(r0, r1, r2, r3, addr) \
    asm volatile("ldmatrix.sync.aligned.m8n8.x4.shared.b16 {%0,%1,%2,%3}, [%4];" \
        : "=r"(r0), "=r"(r1), "=r"(r2), "=r"(r3) : "r"(addr))
#define MMA16816(c0, c1, c2, c3, a0, a1, a2, a3, b0, b1) \
    asm volatile("mma.sync.aligned.m16n8k16.row.col.f32.bf16.bf16.f32 " \
        "{%0,%1,%2,%3}, {%4,%5,%6,%7}, {%8,%9}, {%0,%1,%2,%3};" \
        : "+f"(c0), "+f"(c1), "+f"(c2), "+f"(c3) \
        : "r"(a0), "r"(a1), "r"(a2), "r"(a3), "r"(b0), "r"(b1))

// ---------------- 0) zero ----------------
__global__ void zero_kernel(float* out) {
    int i = blockIdx.x * blockDim.x + threadIdx.x;
    if (i < MD) { g_s1[i] = 0.0f; g_s2[i] = 0.0f; }
    if (i < 2 * ED) out[i] = 0.0f;
}

// ---------------- conv f32 -> bf16 ----------------
__global__ void conv_kernel(const float* __restrict__ src, __nv_bfloat16* __restrict__ dst, int n4) {
    int i = blockIdx.x * blockDim.x + threadIdx.x;
    if (i >= n4) return;
    float4 v = ((const float4*)src)[i];
    uint32_t lo, hi;
    asm("cvt.rn.bf16x2.f32 %0, %1, %2;" : "=r"(lo) : "f"(v.y), "f"(v.x));
    asm("cvt.rn.bf16x2.f32 %0, %1, %2;" : "=r"(hi) : "f"(v.w), "f"(v.z));
    ((uint2*)dst)[i] = make_uint2(lo, hi);
}

// ---------------- ctx GEMV ----------------
__global__ void ctx_kernel(const float* __restrict__ ctx,
                           const float* __restrict__ Wc1, const float* __restrict__ Wc2,
                           const float* __restrict__ b1, const float* __restrict__ b2) {
    int g = blockIdx.x * (blockDim.x >> 5) + (threadIdx.x >> 5);
    int lane = threadIdx.x & 31;
    int mat = g >> 10, row = g & 1023;
    const float* W = mat ? Wc2 : Wc1;
    const float* b = mat ? b2 : b1;
    float* out = mat ? g_bias2 : g_bias1;
    float acc = 0.0f;
    const float* wr = W + (size_t)row * ED;
    for (int k = lane; k < ED; k += 32) acc += wr[k] * ctx[k];
    #pragma unroll
    for (int o = 16; o > 0; o >>= 1) acc += __shfl_down_sync(0xffffffffu, acc, o);
    if (lane == 0) out[row] = b[row] + acc;
}

// ---------------- bf16 mma.sync GEMM: P = elu(A @ W^T + bias) -------------
// CTA 128x128, BK=64, 2-stage cp.async. 8 warps: 2(M) x 4(N), warp 64x32.
#define BK 64
#define NCHUNK (ED / BK)                 // 16
#define STAGE_BYTES (2 * 128 * 128)      // A 16KB + B 16KB
// smem row: 64 bf16 = 128B = 8 chunks of 16B; swizzle chunk c of row r: c ^ (r&7)

__global__ void __launch_bounds__(256, 2)
gemm_mma_kernel(const __nv_bfloat16* __restrict__ A, const __nv_bfloat16* __restrict__ W,
                const float* __restrict__ bias, __nv_bfloat16* __restrict__ P) {
    extern __shared__ __align__(128) char dyn[];
    __shared__ float bias_s[128];

    const int tid = threadIdx.x;
    const int wid = tid >> 5, lane = tid & 31;
    const int rowBlock = blockIdx.y * 128;
    const int colBlock = blockIdx.x * 128;

    uint32_t sbase = (smem_u32(dyn) + 127u) & ~127u;

    if (tid < 128) bias_s[tid] = bias[colBlock + tid];

    const int warp_m = wid & 1;      // 0..1  -> m offset 0/64
    const int warp_n = wid >> 1;     // 0..3  -> n offset 0/32/64/96
    const int m0 = warp_m * 64;
    const int n0 = warp_n * 32;

    float acc[4][4][4];              // [mi][nt][4]
    #pragma unroll
    for (int i = 0; i < 4; i++)
        #pragma unroll
        for (int j = 0; j < 4; j++)
            #pragma unroll
            for (int q = 0; q < 4; q++) acc[i][j][q] = 0.0f;

    // cooperative cp.async loader: A rows 0..127, B rows 0..127, 8 16B-chunks/row
    auto load_chunk = [&](int chunk, int stage) {
        const int k0 = chunk * BK;
        uint32_t ab = sbase + stage * STAGE_BYTES;
        uint32_t bb = ab + 16384;
        #pragma unroll
        for (int l = 0; l < 4; l++) {
            int i = tid + l * 256;           // 0..1023
            int r = i >> 3, c = i & 7;
            uint32_t dst = ab + (uint32_t)(r * 128) + (uint32_t)((c ^ (r & 7)) << 4);
            CP_ASYNC16(dst, A + (size_t)(rowBlock + r) * ED + k0 + c * 8);
        }
        #pragma unroll
        for (int l = 0; l < 4; l++) {
            int i = tid + l * 256;
            int r = i >> 3, c = i & 7;
            uint32_t dst = bb + (uint32_t)(r * 128) + (uint32_t)((c ^ (r & 7)) << 4);
            CP_ASYNC16(dst, W + (size_t)(colBlock + r) * ED + k0 + c * 8);
        }
        CP_COMMIT();
    };

    load_chunk(0, 0);
    load_chunk(1, 1);

    // per-lane ldmatrix row precompute
    const int lr = lane & 7, sub = lane >> 3;
    // A fragment rows: sub0/1 -> rows +0/+8 (k-lo), sub2/3 -> rows +0/+8 (k-hi)
    int arow[4], brow[2];
    uint32_t aswz[4], bswz[2];
    #pragma unroll
    for (int mi = 0; mi < 4; mi++) {
        int r = m0 + mi * 16 + ((sub & 1) << 3) + lr;
        arow[mi] = r * 128; aswz[mi] = (uint32_t)(r & 7);
    }
    const uint32_t achunkbit = (uint32_t)(sub >> 1);
    #pragma unroll
    for (int p = 0; p < 2; p++) {
        int r = n0 + p * 16 + ((sub >> 1) << 3) + lr;
        brow[p] = r * 128; bswz[p] = (uint32_t)(r & 7);
    }
    const uint32_t bchunkbit = (uint32_t)(sub & 1);

    for (int ch = 0; ch < NCHUNK; ch++) {
        const int s = ch & 1;
        CP_WAIT1();
        __syncthreads();
        uint32_t ab = sbase + s * STAGE_BYTES;
        uint32_t bb = ab + 16384;

        #pragma unroll
        for (int ks = 0; ks < 4; ks++) {
            uint32_t a[4][4], b[8];
            #pragma unroll
            for (int mi = 0; mi < 4; mi++) {
                uint32_t addr = ab + (uint32_t)arow[mi] +
                                ((((uint32_t)(ks << 1) | achunkbit) ^ aswz[mi]) << 4);
                LDMATRIX_X4(a[mi][0], a[mi][1], a[mi][2], a[mi][3], addr);
            }
            #pragma unroll
            for (int p = 0; p < 2; p++) {
                uint32_t addr = bb + (uint32_t)brow[p] +
                                ((((uint32_t)(ks << 1) | bchunkbit) ^ bswz[p]) << 4);
                LDMATRIX_X4(b[p * 4 + 0], b[p * 4 + 1], b[p * 4 + 2], b[p * 4 + 3], addr);
            }
            #pragma unroll
            for (int mi = 0; mi < 4; mi++)
                #pragma unroll
                for (int nt = 0; nt < 4; nt++)
                    MMA16816(acc[mi][nt][0], acc[mi][nt][1], acc[mi][nt][2], acc[mi][nt][3],
                             a[mi][0], a[mi][1], a[mi][2], a[mi][3],
                             b[nt * 2], b[nt * 2 + 1]);
        }
        __syncthreads();
        if (ch < NCHUNK - 2) load_chunk(ch + 2, s);
        else CP_COMMIT();
    }

    // epilogue: bias + elu -> bf16 stores (bf16x2 per thread position)
    const int qrow = lane >> 2;          // 0..7
    const int qcol = (lane & 3) * 2;     // 0,2,4,6
    #pragma unroll
    for (int mi = 0; mi < 4; mi++) {
        #pragma unroll
        for (int nt = 0; nt < 4; nt++) {
            int col = n0 + nt * 8 + qcol;
            float bv0 = bias_s[col], bv1 = bias_s[col + 1];
            int r0 = rowBlock + m0 + mi * 16 + qrow;
            float x0 = elu1(acc[mi][nt][0] + bv0);
            float x1 = elu1(acc[mi][nt][1] + bv1);
            float x2 = elu1(acc[mi][nt][2] + bv0);
            float x3 = elu1(acc[mi][nt][3] + bv1);
            uint32_t p01, p23;
            asm("cvt.rn.bf16x2.f32 %0, %1, %2;" : "=r"(p01) : "f"(x1), "f"(x0));
            asm("cvt.rn.bf16x2.f32 %0, %1, %2;" : "=r"(p23) : "f"(x3), "f"(x2));
            *(uint32_t*)(P + (size_t)r0 * MD + colBlock + col) = p01;
            *(uint32_t*)(P + (size_t)(r0 + 8) * MD + colBlock + col) = p23;
        }
    }
}

// ---------------- column sums of bf16 P -> f32 S ----------------
__global__ void colsum_kernel() {
    int mat = blockIdx.y;
    const uint32_t* Pp = (const uint32_t*)(mat ? g_p2 : g_p1);
    float* S = mat ? g_s2 : g_s1;
    int t = threadIdx.x;
    int r0 = blockIdx.x * 128;
    float a0 = 0.0f, a1 = 0.0f;
    for (int r = r0; r < r0 + 128; r++) {
        uint32_t u = Pp[(size_t)r * 512 + t];
        __nv_bfloat162 h = *(__nv_bfloat162*)&u;
        a0 += __bfloat162float(h.x);
        a1 += __bfloat162float(h.y);
    }
    atomicAdd(&S[2 * t], a0);
    atomicAdd(&S[2 * t + 1], a1);
}

// ---------------- logits GEMV ----------------
__global__ void logits_kernel() {
    __shared__ float s[MD];
    int mat = blockIdx.x >> 10;
    const uint32_t* P = (const uint32_t*)(mat ? g_p2 : g_p1);
    const float* S = mat ? g_s1 : g_s2;
    float* L = g_logits + mat * AR;

    for (int i = threadIdx.x; i < MD; i += blockDim.x) s[i] = S[i];
    __syncthreads();

    int wid = threadIdx.x >> 5, lane = threadIdx.x & 31;
    int row = (blockIdx.x & 1023) * 8 + wid;
    const uint32_t* p = P + (size_t)row * 512;
    float acc = 0.0f;
    #pragma unroll 4
    for (int k = lane; k < 512; k += 32) {
        uint32_t u = p[k];
        __nv_bfloat162 h = *(__nv_bfloat162*)&u;
        acc += __bfloat162float(h.x) * s[2 * k] + __bfloat162float(h.y) * s[2 * k + 1];
    }
    #pragma unroll
    for (int o = 16; o > 0; o >>= 1) acc += __shfl_down_sync(0xffffffffu, acc, o);
    if (lane == 0) L[row] = acc;
}

// ---------------- softmax ----------------
__global__ void softmax_kernel() {
    __shared__ float red[1024];
    int mat = blockIdx.x;
    const float* L = g_logits + mat * AR;
    float* W = g_wexp + mat * AR;
    int t = threadIdx.x;
    float m = -INFINITY;
    for (int i = t; i < AR; i += 1024) m = fmaxf(m, L[i]);
    red[t] = m; __syncthreads();
    for (int o = 512; o > 0; o >>= 1) { if (t < o) red[t] = fmaxf(red[t], red[t + o]); __syncthreads(); }
    m = red[0]; __syncthreads();
    float z = 0.0f;
    for (int i = t; i < AR; i += 1024) z += expf(L[i] - m);
    red[t] = z; __syncthreads();
    for (int o = 512; o > 0; o >>= 1) { if (t < o) red[t] += red[t + o]; __syncthreads(); }
    float inv = 1.0f / red[0];
    for (int i = t; i < AR; i += 1024) W[i] = expf(L[i] - m) * inv;
}

// ---------------- att = seq.T @ w ----------------
__global__ void att_kernel(const float* __restrict__ seq1, const float* __restrict__ seq2,
                           float* __restrict__ out) {
    int mat = blockIdx.z;
    const float* Sq = mat ? seq2 : seq1;
    const float* W = g_wexp + mat * AR;
    int c = blockIdx.x * 256 + threadIdx.x;
    int r0 = blockIdx.y * 512;
    float acc0 = 0.0f, acc1 = 0.0f;
    #pragma unroll 4
    for (int r = r0; r < r0 + 512; r += 2) {
        acc0 += Sq[(size_t)r * ED + c] * W[r];
        acc1 += Sq[(size_t)(r + 1) * ED + c] * W[r + 1];
    }
    atomicAdd(&out[mat * ED + c], acc0 + acc1);
}

// ---------------- launch ----------------
extern "C" void kernel_launch(void* const* d_in, const int* in_sizes, int n_in,
                              void* d_out, int out_size) {
    const float* seq1 = (const float*)d_in[0];
    const float* seq2 = (const float*)d_in[1];
    const float* ctx  = (const float*)d_in[2];
    const float* Wc1  = (const float*)d_in[3];
    const float* Wc2  = (const float*)d_in[4];
    const float* W1   = (const float*)d_in[5];
    const float* b1   = (const float*)d_in[6];
    const float* W2   = (const float*)d_in[7];
    const float* b2   = (const float*)d_in[8];
    float* out = (float*)d_out;

    __nv_bfloat16 *a1, *a2, *wb1, *wb2, *p1, *p2;
    float *bias1, *bias2;
    cudaGetSymbolAddress((void**)&a1, g_a1);
    cudaGetSymbolAddress((void**)&a2, g_a2);
    cudaGetSymbolAddress((void**)&wb1, g_wb1);
    cudaGetSymbolAddress((void**)&wb2, g_wb2);
    cudaGetSymbolAddress((void**)&p1, g_p1);
    cudaGetSymbolAddress((void**)&p2, g_p2);
    cudaGetSymbolAddress((void**)&bias1, g_bias1);
    cudaGetSymbolAddress((void**)&bias2, g_bias2);

    size_t smem = 2 * STAGE_BYTES + 128;
    cudaFuncSetAttribute(gemm_mma_kernel, cudaFuncAttributeMaxDynamicSharedMemorySize, (int)smem);

    zero_kernel<<<16, 256>>>(out);
    ctx_kernel<<<256, 256>>>(ctx, Wc1, Wc2, b1, b2);

    int nseq4 = AR * ED / 4, nw4 = MD * ED / 4;
    conv_kernel<<<(nseq4 + 255) / 256, 256>>>(seq1, a1, nseq4);
    conv_kernel<<<(nseq4 + 255) / 256, 256>>>(seq2, a2, nseq4);
    conv_kernel<<<(nw4 + 255) / 256, 256>>>(W1, wb1, nw4);
    conv_kernel<<<(nw4 + 255) / 256, 256>>>(W2, wb2, nw4);

    dim3 ggrid(MD / 128, AR / 128);   // (8, 64)
    gemm_mma_kernel<<<ggrid, 256, smem>>>(a1, wb1, bias1, p1);
    gemm_mma_kernel<<<ggrid, 256, smem>>>(a2, wb2, bias2, p2);

    colsum_kernel<<<dim3(64, 2), 512>>>();
    logits_kernel<<<2048, 256>>>();
    softmax_kernel<<<2, 1024>>>();
    att_kernel<<<dim3(ED / 256, AR / 512, 2), 256>>>(seq1, seq2, out);
}